// round 12
// baseline (speedup 1.0000x reference)
#include <cuda_runtime.h>
#include <cuda_bf16.h>
#include <math.h>
#include <stdint.h>

// LSTM: T=1024, B=64, I=256, H=512, O=5
// out = [outputs (T*B*O) | h_T (B*H) | c_T (B*H)]

#define TT 1024
#define BB 64
#define II 256
#define HH 512
#define G4 2048
#define OO 5
#define REC_CTAS 128

// ---- device scratch ----
__device__ float g_xgT[(size_t)TT * G4 * BB];     // [T][4H][B]
__device__ float g_hsT[(size_t)TT * HH * BB];     // [T][H][B]
// Whh split-bf16 per rec-CTA tile: [(m*2+copy)*16 + r][512], r = gate*4+u
__device__ __nv_bfloat16 g_Abf[128 * 2 * 16 * 512];
// h split-bf16 TRANSPOSED, ping-pong: [pp 2][copy 2][b 64][k 512]
__device__ __nv_bfloat16 g_hT2[2 * 2 * 64 * 512];
// Wih split-bf16: [copy 2][R 2048][k 256]
__device__ __nv_bfloat16 g_wihbf[2 * 2048 * 256];
// x split-bf16, transposed per t: [t 1024][copy 2][k 256][b 64]
__device__ __nv_bfloat16 g_xbf[(size_t)1024 * 2 * 256 * 64];
__device__ unsigned g_bar_count;
__device__ volatile unsigned g_bar_gen;

__device__ __forceinline__ float sigf(float x) {
    return 1.0f / (1.0f + __expf(-x));
}
__device__ __forceinline__ float tanhfast(float x) {
    x = fminf(fmaxf(x, -15.0f), 15.0f);
    float e = __expf(2.0f * x);
    return __fdividef(e - 1.0f, e + 1.0f);
}

__device__ __forceinline__ void cpa16(uint32_t saddr, const void* gptr) {
    asm volatile("cp.async.cg.shared.global [%0], [%1], 16;"
                 :: "r"(saddr), "l"(gptr));
}
#define CP_COMMIT() asm volatile("cp.async.commit_group;")
#define CP_WAIT(n)  asm volatile("cp.async.wait_group %0;" :: "n"(n))

#define LDSM_X4(r0,r1,r2,r3,addr) \
    asm volatile("ldmatrix.sync.aligned.m8n8.x4.shared.b16 {%0,%1,%2,%3}, [%4];" \
        : "=r"(r0),"=r"(r1),"=r"(r2),"=r"(r3) : "r"(addr))
#define LDSM_X2T(r0,r1,addr) \
    asm volatile("ldmatrix.sync.aligned.m8n8.x2.trans.shared.b16 {%0,%1}, [%2];" \
        : "=r"(r0),"=r"(r1) : "r"(addr))
#define MMA16816(d0,d1,d2,d3,a0,a1,a2,a3,b0,b1) \
    asm volatile("mma.sync.aligned.m16n8k16.row.col.f32.bf16.bf16.f32 " \
        "{%0,%1,%2,%3}, {%4,%5,%6,%7}, {%8,%9}, {%0,%1,%2,%3};" \
        : "+f"(d0),"+f"(d1),"+f"(d2),"+f"(d3) \
        : "r"(a0),"r"(a1),"r"(a2),"r"(a3),"r"(b0),"r"(b1))

__device__ __forceinline__ void grid_sync() {
    __syncthreads();
    if (threadIdx.x == 0) {
        unsigned old = g_bar_gen;
        __threadfence();
        unsigned t = atomicAdd(&g_bar_count, 1u);
        if (t == REC_CTAS - 1) {
            atomicExch(&g_bar_count, 0u);
            __threadfence();
            g_bar_gen = old + 1u;
        } else {
            while (g_bar_gen == old) { }
            __threadfence();
        }
    }
    __syncthreads();
}

// ============================================================================
// Kernel P1: Whh -> split-bf16 rec tiles (R = gate*512 + m*4 + u)
// ============================================================================
__global__ void prep_whh(const float* __restrict__ Whh) {
    int R = blockIdx.x;
    int gate = R >> 9, rem = R & 511;
    int m = rem >> 2, u = rem & 3;
    int r = gate * 4 + u;
    for (int k = threadIdx.x; k < HH; k += blockDim.x) {
        float w = Whh[(size_t)R * HH + k];
        __nv_bfloat16 hi = __float2bfloat16(w);
        __nv_bfloat16 lo = __float2bfloat16(w - __bfloat162float(hi));
        g_Abf[((size_t)(m * 2 + 0) * 16 + r) * HH + k] = hi;
        g_Abf[((size_t)(m * 2 + 1) * 16 + r) * HH + k] = lo;
    }
}

// ============================================================================
// Kernel P2: Wih -> split-bf16 [copy][R][k]
// ============================================================================
__global__ void prep_wih(const float* __restrict__ Wih) {
    int R = blockIdx.x;
    for (int k = threadIdx.x; k < II; k += blockDim.x) {
        float w = Wih[(size_t)R * II + k];
        __nv_bfloat16 hi = __float2bfloat16(w);
        __nv_bfloat16 lo = __float2bfloat16(w - __bfloat162float(hi));
        g_wihbf[(size_t)R * II + k] = hi;
        g_wihbf[(size_t)(2048 + R) * II + k] = lo;
    }
}

// ============================================================================
// Kernel P3: x[t] -> split-bf16 transposed [t][copy][k][b]
// ============================================================================
__global__ void prep_x(const float* __restrict__ x) {
    __shared__ float xs[64 * 257];
    const int t = blockIdx.x, tid = threadIdx.x;
    for (int idx = tid; idx < 64 * 64; idx += 256) {
        int b = idx >> 6, i = idx & 63;
        float4 v = *(const float4*)(x + ((size_t)t * BB + b) * II + i * 4);
        xs[b * 257 + i*4 + 0] = v.x; xs[b * 257 + i*4 + 1] = v.y;
        xs[b * 257 + i*4 + 2] = v.z; xs[b * 257 + i*4 + 3] = v.w;
    }
    __syncthreads();
    __nv_bfloat16* dst = g_xbf + (size_t)t * (2 * 256 * 64);
    for (int idx = tid; idx < 256 * 64; idx += 256) {
        int k = idx >> 6, b = idx & 63;
        float v = xs[b * 257 + k];
        __nv_bfloat16 hi = __float2bfloat16(v);
        __nv_bfloat16 lo = __float2bfloat16(v - __bfloat162float(hi));
        dst[(size_t)k * 64 + b] = hi;
        dst[(size_t)(256 + k) * 64 + b] = lo;
    }
}

// ============================================================================
// Kernel 1: pregemm via HMMA (unchanged from R11; 144B A-row stride)
// ============================================================================
#define PG_ACOPY 18432
#define PG_AOFF  0
#define PG_BOFF  36864
#define PG_BCOPY 9216
#define PG_CHUNK 55296
#define PG_BIAS  (2 * PG_CHUNK)
#define PG_SMEM  (PG_BIAS + 512 + 256)

__device__ __forceinline__ void pg_stage(uint32_t sb, int buf, int mbG, int t,
                                         int kc, int tid) {
    uint32_t dst = sb + buf * PG_CHUNK;
    #pragma unroll
    for (int j = 0; j < 8; j++) {
        int idx = j * 256 + tid;
        int c2 = idx >> 10, rem = idx & 1023;
        int r = rem >> 3, i = rem & 7;
        cpa16(dst + PG_AOFF + c2 * PG_ACOPY + r * 144 + i * 16,
              g_wihbf + ((size_t)(c2 * 2048 + mbG * 128 + r)) * II + kc * 64 + i * 8);
    }
    #pragma unroll
    for (int j = 0; j < 4; j++) {
        int idx = j * 256 + tid;
        int c2 = idx >> 9, rem = idx & 511;
        int k = rem >> 3, i = rem & 7;
        cpa16(dst + PG_BOFF + c2 * PG_BCOPY + k * 144 + i * 16,
              g_xbf + ((size_t)t * 2 + c2) * (256 * 64) + (size_t)(kc * 64 + k) * 64 + i * 8);
    }
    CP_COMMIT();
}

__global__ void __launch_bounds__(256, 1) pregemm_mma(
    const float* __restrict__ bih, const float* __restrict__ bhh)
{
    extern __shared__ char smraw[];
    uint32_t sb0 = (uint32_t)__cvta_generic_to_shared(smraw);
    uint32_t sb  = (sb0 + 127u) & ~127u;
    char* smem = smraw + (sb - sb0);
    float* bsm = (float*)(smem + PG_BIAS);

    const int t   = blockIdx.x >> 4;
    const int mbG = blockIdx.x & 15;
    const int tid = threadIdx.x;
    const int wid = tid >> 5;
    const int lane = tid & 31;

    if (tid < 128) {
        int R = mbG * 128 + tid;
        bsm[tid] = bih[R] + bhh[R];
    }

    pg_stage(sb, 0, mbG, t, 0, tid);
    pg_stage(sb, 1, mbG, t, 1, tid);

    float d[8][4];
    #pragma unroll
    for (int i = 0; i < 8; i++)
        #pragma unroll
        for (int j = 0; j < 4; j++) d[i][j] = 0.0f;

    const uint32_t aRel = (uint32_t)(lane & 15) * 144 + (uint32_t)(lane >> 4) * 16;
    const uint32_t bRel = (uint32_t)(lane & 15) * 144 + (uint32_t)wid * 16;

    #pragma unroll
    for (int c = 0; c < 4; c++) {
        if (c < 3) CP_WAIT(1); else CP_WAIT(0);
        __syncthreads();
        uint32_t buf = sb + (c & 1) * PG_CHUNK;
        uint32_t aB = buf + PG_AOFF + aRel;
        uint32_t bB = buf + PG_BOFF + bRel;
        #pragma unroll
        for (int ks = 0; ks < 4; ks++) {
            uint32_t bh0, bh1, bl0, bl1;
            LDSM_X2T(bh0, bh1, bB + ks * 2304);
            LDSM_X2T(bl0, bl1, bB + PG_BCOPY + ks * 2304);
            #pragma unroll
            for (int mb = 0; mb < 8; mb++) {
                uint32_t ah0,ah1,ah2,ah3, al0,al1,al2,al3;
                LDSM_X4(ah0,ah1,ah2,ah3, aB + mb * (16*144) + ks * 32);
                LDSM_X4(al0,al1,al2,al3, aB + PG_ACOPY + mb * (16*144) + ks * 32);
                MMA16816(d[mb][0],d[mb][1],d[mb][2],d[mb][3], ah0,ah1,ah2,ah3, bh0,bh1);
                MMA16816(d[mb][0],d[mb][1],d[mb][2],d[mb][3], ah0,ah1,ah2,ah3, bl0,bl1);
                MMA16816(d[mb][0],d[mb][1],d[mb][2],d[mb][3], al0,al1,al2,al3, bh0,bh1);
            }
        }
        __syncthreads();
        if (c < 2) pg_stage(sb, c & 1, mbG, t, c + 2, tid);
    }

    float* outp = g_xgT + (size_t)t * (G4 * BB);
    const int c0 = wid * 8 + (lane & 3) * 2;
    #pragma unroll
    for (int mb = 0; mb < 8; mb++) {
        int r0 = mb * 16 + (lane >> 2);
        int R0 = mbG * 128 + r0;
        float b0 = bsm[r0], b1 = bsm[r0 + 8];
        *(float2*)(outp + (size_t)R0 * BB + c0) =
            make_float2(d[mb][0] + b0, d[mb][1] + b0);
        *(float2*)(outp + (size_t)(R0 + 8) * BB + c0) =
            make_float2(d[mb][2] + b1, d[mb][3] + b1);
    }
}

// ============================================================================
// Kernel 2: persistent HMMA recurrence, ZERO per-step staging.
// B fragments loaded directly from L2 (__ldcg) out of transposed h [c][b][k]:
//   lane reg0 = h[n][k0..k0+1], reg1 = h[n][k0+8..k0+9]; n=wid*8+(lane>>2),
//   k0 = ks*16 + (lane&3)*2.  reg0+reg1 of lanes 0-3 fill whole 32B sectors.
// A (Whh tiles) resident in smem; per step: 32 ks x (4 LDG.32 + 2 LDSM + 3 MMA).
// ============================================================================
#define ASM_OFF   0
#define ASM_COPY  16640           // 16 rows * 1040B
#define GSM_OFF   33280
#define GSM_STR   66
#define CSM_OFF   (GSM_OFF + 16 * GSM_STR * 4)   // 37504
#define REC_SMEM  (CSM_OFF + 1024 + 256)

__global__ void __launch_bounds__(256, 1) lstm_rec_mma(
    float* __restrict__ d_out, int out_size)
{
    extern __shared__ char smraw[];
    uint32_t sb0 = (uint32_t)__cvta_generic_to_shared(smraw);
    uint32_t sb  = (sb0 + 127u) & ~127u;
    char* smem = smraw + (sb - sb0);

    float* gsm = (float*)(smem + GSM_OFF);
    float* csm = (float*)(smem + CSM_OFF);

    const int m    = blockIdx.x;
    const int tid  = threadIdx.x;
    const int wid  = tid >> 5;
    const int lane = tid & 31;
    const int b    = tid & 63;
    const int u    = tid >> 6;

    // one-time: A tiles -> smem (both copies), 1040B row stride (16B aligned,
    // 260 words % 32 = 4 -> conflict-free ldmatrix)
    for (int idx = tid; idx < 2 * 16 * 64; idx += 256) {
        int c = idx >> 10, rem = idx & 1023;
        int r = rem >> 6, i = rem & 63;
        uint4 v = *(const uint4*)(g_Abf + ((size_t)(m*2+c)*16 + r) * HH + i*8);
        *(uint4*)(smem + ASM_OFF + c*ASM_COPY + r*1040 + i*16) = v;
    }
    // zero transposed h ping-pong (256KB total across 128 CTAs)
    for (int i = m * 256 + tid; i < (2*2*64*512)/8; i += REC_CTAS * 256)
        ((uint4*)g_hT2)[i] = make_uint4(0, 0, 0, 0);
    csm[u * 64 + b] = 0.0f;
    __threadfence();
    grid_sync();

    const uint32_t aBase = sb + ASM_OFF + (uint32_t)(lane & 15) * 1040
                         + (uint32_t)(lane >> 4) * 16;
    // per-lane B base offsets into the transposed h plane
    const int nrow = wid * 8 + (lane >> 2);
    const int koff = (lane & 3) * 2;

    int cur = 0;
    for (int step = 0; step < TT; step++) {
        const __nv_bfloat16* hp  = g_hT2 + (size_t)cur * (2 * 64 * 512);
        const __nv_bfloat16* hhi = hp + (size_t)nrow * 512 + koff;
        const __nv_bfloat16* hlo = hhi + 64 * 512;

        const float* xgs = g_xgT + (size_t)step * (G4 * BB);
        int gu = m * 4 + u;
        float xg0 = __ldcs(xgs + (size_t)(0*HH + gu) * BB + b);
        float xg1 = __ldcs(xgs + (size_t)(1*HH + gu) * BB + b);
        float xg2 = __ldcs(xgs + (size_t)(2*HH + gu) * BB + b);
        float xg3 = __ldcs(xgs + (size_t)(3*HH + gu) * BB + b);

        float d0 = 0.f, d1 = 0.f, d2 = 0.f, d3 = 0.f;

        #pragma unroll 8
        for (int ks = 0; ks < 32; ks++) {
            uint32_t bh0 = __ldcg((const unsigned*)(hhi + ks * 16));
            uint32_t bh1 = __ldcg((const unsigned*)(hhi + ks * 16 + 8));
            uint32_t bl0 = __ldcg((const unsigned*)(hlo + ks * 16));
            uint32_t bl1 = __ldcg((const unsigned*)(hlo + ks * 16 + 8));
            uint32_t ah0,ah1,ah2,ah3, al0,al1,al2,al3;
            LDSM_X4(ah0,ah1,ah2,ah3, aBase + ks*32);
            LDSM_X4(al0,al1,al2,al3, aBase + ASM_COPY + ks*32);
            MMA16816(d0,d1,d2,d3, ah0,ah1,ah2,ah3, bh0,bh1);
            MMA16816(d0,d1,d2,d3, ah0,ah1,ah2,ah3, bl0,bl1);
            MMA16816(d0,d1,d2,d3, al0,al1,al2,al3, bh0,bh1);
        }

        {
            int r0 = lane >> 2;
            int cB = wid * 8 + (lane & 3) * 2;
            *(float2*)&gsm[r0 * GSM_STR + cB]       = make_float2(d0, d1);
            *(float2*)&gsm[(r0 + 8) * GSM_STR + cB] = make_float2(d2, d3);
        }
        __syncthreads();

        {
            float p0 = gsm[(0*4 + u) * GSM_STR + b] + xg0;
            float p1 = gsm[(1*4 + u) * GSM_STR + b] + xg1;
            float p2 = gsm[(2*4 + u) * GSM_STR + b] + xg2;
            float p3 = gsm[(3*4 + u) * GSM_STR + b] + xg3;
            float ig = sigf(p0), fg = sigf(p1);
            float gg = tanhfast(p2), og = sigf(p3);
            float c  = fmaf(fg, csm[u * 64 + b], ig * gg);
            float h  = og * tanhfast(c);
            csm[u * 64 + b] = c;
            __stcs(&g_hsT[(size_t)step * (HH*BB) + (size_t)gu * BB + b], h);
            __nv_bfloat16 hh = __float2bfloat16(h);
            __nv_bfloat16 hl = __float2bfloat16(h - __bfloat162float(hh));
            int nxt = cur ^ 1;
            __nv_bfloat16* hw = g_hT2 + (size_t)nxt * (2 * 64 * 512);
            hw[(size_t)b * 512 + gu] = hh;                    // hi plane
            hw[(size_t)(64 + b) * 512 + gu] = hl;             // lo plane
            if (step == TT - 1 && out_size >= TT*BB*OO + 2*BB*HH) {
                d_out[TT*BB*OO + (size_t)b * HH + gu] = h;
                d_out[TT*BB*OO + BB*HH + (size_t)b * HH + gu] = c;
            }
        }
        __threadfence();
        grid_sync();
        cur ^= 1;
    }
}

// ============================================================================
// Kernel 3: FC epilogue
// ============================================================================
__global__ void __launch_bounds__(320) fc_kernel(
    const float* __restrict__ fcw, const float* __restrict__ fcb,
    float* __restrict__ out)
{
    __shared__ float wsm[OO][HH];
    __shared__ float bsm[OO];
    const int t = blockIdx.x, tid = threadIdx.x;
    for (int s = tid; s < OO * HH; s += 320) wsm[s / HH][s % HH] = fcw[s];
    if (tid < OO) bsm[tid] = fcb[tid];
    __syncthreads();
    const int o = tid >> 6, b = tid & 63;
    const float* hp = g_hsT + (size_t)t * (HH * BB) + b;
    float acc = bsm[o];
    #pragma unroll 8
    for (int k = 0; k < HH; k++)
        acc = fmaf(__ldcs(hp + (size_t)k * BB), wsm[o][k], acc);
    out[(size_t)t * (BB * OO) + b * OO + o] = acc;
}

// ============================================================================
extern "C" void kernel_launch(void* const* d_in, const int* in_sizes, int n_in,
                              void* d_out, int out_size) {
    const float* x   = (const float*)d_in[0];
    const float* Wih = (const float*)d_in[1];
    const float* Whh = (const float*)d_in[2];
    const float* bih = (const float*)d_in[3];
    const float* bhh = (const float*)d_in[4];
    const float* fcw = (const float*)d_in[5];
    const float* fcb = (const float*)d_in[6];
    float* out = (float*)d_out;

    cudaFuncSetAttribute(lstm_rec_mma,
                         cudaFuncAttributeMaxDynamicSharedMemorySize, REC_SMEM);
    cudaFuncSetAttribute(pregemm_mma,
                         cudaFuncAttributeMaxDynamicSharedMemorySize, PG_SMEM);

    prep_whh<<<G4, 128>>>(Whh);
    prep_wih<<<G4, 128>>>(Wih);
    prep_x<<<TT, 256>>>(x);
    pregemm_mma<<<TT * 16, 256, PG_SMEM>>>(bih, bhh);
    lstm_rec_mma<<<REC_CTAS, 256, REC_SMEM>>>(out, out_size);
    fc_kernel<<<TT, 320>>>(fcw, fcb, out);
}

// round 13
// speedup vs baseline: 1.7379x; 1.7379x over previous
#include <cuda_runtime.h>
#include <cuda_bf16.h>
#include <math.h>
#include <stdint.h>

// LSTM: T=1024, B=64, I=256, H=512, O=5
// out = [outputs (T*B*O) | h_T (B*H) | c_T (B*H)]

#define TT 1024
#define BB 64
#define II 256
#define HH 512
#define G4 2048
#define OO 5
#define REC_CTAS 128

// ---- device scratch ----
__device__ float g_xgT[(size_t)TT * G4 * BB];     // [T][4H][B]
__device__ float g_hsT[(size_t)TT * HH * BB];     // [T][H][B]
// Whh split-bf16 per rec-CTA tile: [(m*2+copy)*16 + r][512], r = gate*4+u
__device__ __nv_bfloat16 g_Abf[128 * 2 * 16 * 512];
// h split-bf16, PADDED ldmatrix-ready, ping-pong: [pp 2][copy 2][k 512][72]
__device__ __align__(16) __nv_bfloat16 g_hbf[2 * 2 * 512 * 72];
// Wih split-bf16: [copy 2][R 2048][k 256]
__device__ __nv_bfloat16 g_wihbf[2 * 2048 * 256];
// x split-bf16, transposed per t: [t 1024][copy 2][k 256][b 64]
__device__ __nv_bfloat16 g_xbf[(size_t)1024 * 2 * 256 * 64];
__device__ unsigned g_bar_count;
__device__ volatile unsigned g_bar_gen;

__device__ __forceinline__ float sigf(float x) {
    return 1.0f / (1.0f + __expf(-x));
}
__device__ __forceinline__ float tanhfast(float x) {
    x = fminf(fmaxf(x, -15.0f), 15.0f);
    float e = __expf(2.0f * x);
    return __fdividef(e - 1.0f, e + 1.0f);
}

__device__ __forceinline__ void cpa16(uint32_t saddr, const void* gptr) {
    asm volatile("cp.async.cg.shared.global [%0], [%1], 16;"
                 :: "r"(saddr), "l"(gptr));
}
#define CP_COMMIT() asm volatile("cp.async.commit_group;")
#define CP_WAIT(n)  asm volatile("cp.async.wait_group %0;" :: "n"(n))

// sm_90-baseline bulk async copy (NOT tcgen05 — compiles on plain sm_103)
__device__ __forceinline__ void bulk_copy(uint32_t dst_smem, const void* src,
                                          uint32_t bytes, uint32_t mbar) {
    asm volatile(
        "cp.async.bulk.shared::cta.global.mbarrier::complete_tx::bytes "
        "[%0], [%1], %2, [%3];"
        :: "r"(dst_smem), "l"(src), "r"(bytes), "r"(mbar) : "memory");
}
#define MBAR_INIT(mb) \
    asm volatile("mbarrier.init.shared.b64 [%0], 1;" :: "r"(mb) : "memory")
#define MBAR_EXPECT_TX(mb, bytes) \
    asm volatile("mbarrier.arrive.expect_tx.shared.b64 _, [%0], %1;" \
                 :: "r"(mb), "r"(bytes) : "memory")
__device__ __forceinline__ void mbar_wait(uint32_t mb, uint32_t parity) {
    asm volatile(
        "{\n\t.reg .pred P;\n"
        "L_%=:\n\t"
        "mbarrier.try_wait.parity.acquire.cta.shared::cta.b64 P, [%0], %1;\n\t"
        "@P bra D_%=;\n\tbra L_%=;\n"
        "D_%=:\n\t}" :: "r"(mb), "r"(parity) : "memory");
}

#define LDSM_X4(r0,r1,r2,r3,addr) \
    asm volatile("ldmatrix.sync.aligned.m8n8.x4.shared.b16 {%0,%1,%2,%3}, [%4];" \
        : "=r"(r0),"=r"(r1),"=r"(r2),"=r"(r3) : "r"(addr))
#define LDSM_X2T(r0,r1,addr) \
    asm volatile("ldmatrix.sync.aligned.m8n8.x2.trans.shared.b16 {%0,%1}, [%2];" \
        : "=r"(r0),"=r"(r1) : "r"(addr))
#define MMA16816(d0,d1,d2,d3,a0,a1,a2,a3,b0,b1) \
    asm volatile("mma.sync.aligned.m16n8k16.row.col.f32.bf16.bf16.f32 " \
        "{%0,%1,%2,%3}, {%4,%5,%6,%7}, {%8,%9}, {%0,%1,%2,%3};" \
        : "+f"(d0),"+f"(d1),"+f"(d2),"+f"(d3) \
        : "r"(a0),"r"(a1),"r"(a2),"r"(a3),"r"(b0),"r"(b1))

__device__ __forceinline__ void grid_sync() {
    __syncthreads();
    if (threadIdx.x == 0) {
        unsigned old = g_bar_gen;
        __threadfence();
        unsigned t = atomicAdd(&g_bar_count, 1u);
        if (t == REC_CTAS - 1) {
            atomicExch(&g_bar_count, 0u);
            __threadfence();
            g_bar_gen = old + 1u;
        } else {
            while (g_bar_gen == old) { }
            __threadfence();
        }
    }
    __syncthreads();
}

// ============================================================================
// Kernel P1: Whh -> split-bf16 rec tiles (R = gate*512 + m*4 + u)
// ============================================================================
__global__ void prep_whh(const float* __restrict__ Whh) {
    int R = blockIdx.x;
    int gate = R >> 9, rem = R & 511;
    int m = rem >> 2, u = rem & 3;
    int r = gate * 4 + u;
    for (int k = threadIdx.x; k < HH; k += blockDim.x) {
        float w = Whh[(size_t)R * HH + k];
        __nv_bfloat16 hi = __float2bfloat16(w);
        __nv_bfloat16 lo = __float2bfloat16(w - __bfloat162float(hi));
        g_Abf[((size_t)(m * 2 + 0) * 16 + r) * HH + k] = hi;
        g_Abf[((size_t)(m * 2 + 1) * 16 + r) * HH + k] = lo;
    }
}

// ============================================================================
// Kernel P2: Wih -> split-bf16 [copy][R][k]
// ============================================================================
__global__ void prep_wih(const float* __restrict__ Wih) {
    int R = blockIdx.x;
    for (int k = threadIdx.x; k < II; k += blockDim.x) {
        float w = Wih[(size_t)R * II + k];
        __nv_bfloat16 hi = __float2bfloat16(w);
        __nv_bfloat16 lo = __float2bfloat16(w - __bfloat162float(hi));
        g_wihbf[(size_t)R * II + k] = hi;
        g_wihbf[(size_t)(2048 + R) * II + k] = lo;
    }
}

// ============================================================================
// Kernel P3: x[t] -> split-bf16 transposed [t][copy][k][b]
// ============================================================================
__global__ void prep_x(const float* __restrict__ x) {
    __shared__ float xs[64 * 257];
    const int t = blockIdx.x, tid = threadIdx.x;
    for (int idx = tid; idx < 64 * 64; idx += 256) {
        int b = idx >> 6, i = idx & 63;
        float4 v = *(const float4*)(x + ((size_t)t * BB + b) * II + i * 4);
        xs[b * 257 + i*4 + 0] = v.x; xs[b * 257 + i*4 + 1] = v.y;
        xs[b * 257 + i*4 + 2] = v.z; xs[b * 257 + i*4 + 3] = v.w;
    }
    __syncthreads();
    __nv_bfloat16* dst = g_xbf + (size_t)t * (2 * 256 * 64);
    for (int idx = tid; idx < 256 * 64; idx += 256) {
        int k = idx >> 6, b = idx & 63;
        float v = xs[b * 257 + k];
        __nv_bfloat16 hi = __float2bfloat16(v);
        __nv_bfloat16 lo = __float2bfloat16(v - __bfloat162float(hi));
        dst[(size_t)k * 64 + b] = hi;
        dst[(size_t)(256 + k) * 64 + b] = lo;
    }
}

// ============================================================================
// Kernel 1: pregemm via HMMA (unchanged from R11)
// ============================================================================
#define PG_ACOPY 18432
#define PG_AOFF  0
#define PG_BOFF  36864
#define PG_BCOPY 9216
#define PG_CHUNK 55296
#define PG_BIAS  (2 * PG_CHUNK)
#define PG_SMEM  (PG_BIAS + 512 + 256)

__device__ __forceinline__ void pg_stage(uint32_t sb, int buf, int mbG, int t,
                                         int kc, int tid) {
    uint32_t dst = sb + buf * PG_CHUNK;
    #pragma unroll
    for (int j = 0; j < 8; j++) {
        int idx = j * 256 + tid;
        int c2 = idx >> 10, rem = idx & 1023;
        int r = rem >> 3, i = rem & 7;
        cpa16(dst + PG_AOFF + c2 * PG_ACOPY + r * 144 + i * 16,
              g_wihbf + ((size_t)(c2 * 2048 + mbG * 128 + r)) * II + kc * 64 + i * 8);
    }
    #pragma unroll
    for (int j = 0; j < 4; j++) {
        int idx = j * 256 + tid;
        int c2 = idx >> 9, rem = idx & 511;
        int k = rem >> 3, i = rem & 7;
        cpa16(dst + PG_BOFF + c2 * PG_BCOPY + k * 144 + i * 16,
              g_xbf + ((size_t)t * 2 + c2) * (256 * 64) + (size_t)(kc * 64 + k) * 64 + i * 8);
    }
    CP_COMMIT();
}

__global__ void __launch_bounds__(256, 1) pregemm_mma(
    const float* __restrict__ bih, const float* __restrict__ bhh)
{
    extern __shared__ char smraw[];
    uint32_t sb0 = (uint32_t)__cvta_generic_to_shared(smraw);
    uint32_t sb  = (sb0 + 127u) & ~127u;
    char* smem = smraw + (sb - sb0);
    float* bsm = (float*)(smem + PG_BIAS);

    const int t   = blockIdx.x >> 4;
    const int mbG = blockIdx.x & 15;
    const int tid = threadIdx.x;
    const int wid = tid >> 5;
    const int lane = tid & 31;

    if (tid < 128) {
        int R = mbG * 128 + tid;
        bsm[tid] = bih[R] + bhh[R];
    }

    pg_stage(sb, 0, mbG, t, 0, tid);
    pg_stage(sb, 1, mbG, t, 1, tid);

    float d[8][4];
    #pragma unroll
    for (int i = 0; i < 8; i++)
        #pragma unroll
        for (int j = 0; j < 4; j++) d[i][j] = 0.0f;

    const uint32_t aRel = (uint32_t)(lane & 15) * 144 + (uint32_t)(lane >> 4) * 16;
    const uint32_t bRel = (uint32_t)(lane & 15) * 144 + (uint32_t)wid * 16;

    #pragma unroll
    for (int c = 0; c < 4; c++) {
        if (c < 3) CP_WAIT(1); else CP_WAIT(0);
        __syncthreads();
        uint32_t buf = sb + (c & 1) * PG_CHUNK;
        uint32_t aB = buf + PG_AOFF + aRel;
        uint32_t bB = buf + PG_BOFF + bRel;
        #pragma unroll
        for (int ks = 0; ks < 4; ks++) {
            uint32_t bh0, bh1, bl0, bl1;
            LDSM_X2T(bh0, bh1, bB + ks * 2304);
            LDSM_X2T(bl0, bl1, bB + PG_BCOPY + ks * 2304);
            #pragma unroll
            for (int mb = 0; mb < 8; mb++) {
                uint32_t ah0,ah1,ah2,ah3, al0,al1,al2,al3;
                LDSM_X4(ah0,ah1,ah2,ah3, aB + mb * (16*144) + ks * 32);
                LDSM_X4(al0,al1,al2,al3, aB + PG_ACOPY + mb * (16*144) + ks * 32);
                MMA16816(d[mb][0],d[mb][1],d[mb][2],d[mb][3], ah0,ah1,ah2,ah3, bh0,bh1);
                MMA16816(d[mb][0],d[mb][1],d[mb][2],d[mb][3], ah0,ah1,ah2,ah3, bl0,bl1);
                MMA16816(d[mb][0],d[mb][1],d[mb][2],d[mb][3], al0,al1,al2,al3, bh0,bh1);
            }
        }
        __syncthreads();
        if (c < 2) pg_stage(sb, c & 1, mbG, t, c + 2, tid);
    }

    float* outp = g_xgT + (size_t)t * (G4 * BB);
    const int c0 = wid * 8 + (lane & 3) * 2;
    #pragma unroll
    for (int mb = 0; mb < 8; mb++) {
        int r0 = mb * 16 + (lane >> 2);
        int R0 = mbG * 128 + r0;
        float b0 = bsm[r0], b1 = bsm[r0 + 8];
        *(float2*)(outp + (size_t)R0 * BB + c0) =
            make_float2(d[mb][0] + b0, d[mb][1] + b0);
        *(float2*)(outp + (size_t)(R0 + 8) * BB + c0) =
            make_float2(d[mb][2] + b1, d[mb][3] + b1);
    }
}

// ============================================================================
// Kernel 2: persistent HMMA recurrence, bulk-copy h staging.
// h lives in global already in the padded [copy][k][72] ldmatrix layout;
// per step ONE cp.async.bulk per plane (72KB hi, 72KB lo) -> smem, mbarrier
// complete_tx. Pass 1 (A·Bhi) overlaps the lo-plane transfer.
// ============================================================================
#define HSM_OFF   0
#define HSM_PLANE 73728           // 512 rows * 144B
#define ASM_OFF   147456
#define ASM_COPY  16640
#define GSM_OFF   180736
#define GSM_STR   66
#define CSM_OFF   184960
#define MBAR_OFF  185984
#define REC_SMEM  (186112 + 256)

__global__ void __launch_bounds__(256, 1) lstm_rec_mma(
    float* __restrict__ d_out, int out_size)
{
    extern __shared__ char smraw[];
    uint32_t sb0 = (uint32_t)__cvta_generic_to_shared(smraw);
    uint32_t sb  = (sb0 + 127u) & ~127u;
    char* smem = smraw + (sb - sb0);

    float* gsm = (float*)(smem + GSM_OFF);
    float* csm = (float*)(smem + CSM_OFF);
    const uint32_t mb0 = sb + MBAR_OFF, mb1 = sb + MBAR_OFF + 8;

    const int m    = blockIdx.x;
    const int tid  = threadIdx.x;
    const int wid  = tid >> 5;
    const int lane = tid & 31;
    const int b    = tid & 63;
    const int u    = tid >> 6;

    // one-time: A tiles -> smem (both copies), 1040B row stride
    for (int idx = tid; idx < 2 * 16 * 64; idx += 256) {
        int c = idx >> 10, rem = idx & 1023;
        int r = rem >> 6, i = rem & 63;
        uint4 v = *(const uint4*)(g_Abf + ((size_t)(m*2+c)*16 + r) * HH + i*8);
        *(uint4*)(smem + ASM_OFF + c*ASM_COPY + r*1040 + i*16) = v;
    }
    // zero padded h ping-pong: 2*2*512*72 bf16 = 36864 uint4
    for (int i = m * 256 + tid; i < 36864; i += REC_CTAS * 256)
        ((uint4*)g_hbf)[i] = make_uint4(0, 0, 0, 0);
    csm[u * 64 + b] = 0.0f;
    if (tid == 0) { MBAR_INIT(mb0); MBAR_INIT(mb1); }
    __threadfence();
    grid_sync();

    const uint32_t aBase = sb + ASM_OFF + (uint32_t)(lane & 15) * 1040
                         + (uint32_t)(lane >> 4) * 16;
    const uint32_t bBase = sb + HSM_OFF + (uint32_t)(lane & 15) * 144
                         + (uint32_t)wid * 16;

    int cur = 0;
    for (int step = 0; step < TT; step++) {
        const __nv_bfloat16* hsrc = g_hbf + (size_t)cur * (2 * 512 * 72);
        if (tid == 0) {
            MBAR_EXPECT_TX(mb0, HSM_PLANE);
            bulk_copy(sb + HSM_OFF, hsrc, HSM_PLANE, mb0);
            MBAR_EXPECT_TX(mb1, HSM_PLANE);
            bulk_copy(sb + HSM_OFF + HSM_PLANE, hsrc + 512 * 72, HSM_PLANE, mb1);
        }

        const float* xgs = g_xgT + (size_t)step * (G4 * BB);
        int gu = m * 4 + u;
        float xg0 = __ldcs(xgs + (size_t)(0*HH + gu) * BB + b);
        float xg1 = __ldcs(xgs + (size_t)(1*HH + gu) * BB + b);
        float xg2 = __ldcs(xgs + (size_t)(2*HH + gu) * BB + b);
        float xg3 = __ldcs(xgs + (size_t)(3*HH + gu) * BB + b);

        float d0 = 0.f, d1 = 0.f, d2 = 0.f, d3 = 0.f;

        // pass 1: hi B plane (whi*hhi + wlo*hhi)
        mbar_wait(mb0, step & 1);
        #pragma unroll 8
        for (int ks = 0; ks < 32; ks++) {
            uint32_t ah0,ah1,ah2,ah3, al0,al1,al2,al3, bh0,bh1;
            LDSM_X4(ah0,ah1,ah2,ah3, aBase + ks*32);
            LDSM_X4(al0,al1,al2,al3, aBase + ASM_COPY + ks*32);
            LDSM_X2T(bh0,bh1, bBase + ks*2304);
            MMA16816(d0,d1,d2,d3, ah0,ah1,ah2,ah3, bh0,bh1);
            MMA16816(d0,d1,d2,d3, al0,al1,al2,al3, bh0,bh1);
        }
        // pass 2: lo B plane (whi*hlo)
        mbar_wait(mb1, step & 1);
        #pragma unroll 8
        for (int ks = 0; ks < 32; ks++) {
            uint32_t ah0,ah1,ah2,ah3, bl0,bl1;
            LDSM_X4(ah0,ah1,ah2,ah3, aBase + ks*32);
            LDSM_X2T(bl0,bl1, bBase + HSM_PLANE + ks*2304);
            MMA16816(d0,d1,d2,d3, ah0,ah1,ah2,ah3, bl0,bl1);
        }

        {
            int r0 = lane >> 2;
            int cB = wid * 8 + (lane & 3) * 2;
            *(float2*)&gsm[r0 * GSM_STR + cB]       = make_float2(d0, d1);
            *(float2*)&gsm[(r0 + 8) * GSM_STR + cB] = make_float2(d2, d3);
        }
        __syncthreads();

        {
            float p0 = gsm[(0*4 + u) * GSM_STR + b] + xg0;
            float p1 = gsm[(1*4 + u) * GSM_STR + b] + xg1;
            float p2 = gsm[(2*4 + u) * GSM_STR + b] + xg2;
            float p3 = gsm[(3*4 + u) * GSM_STR + b] + xg3;
            float ig = sigf(p0), fg = sigf(p1);
            float gg = tanhfast(p2), og = sigf(p3);
            float c  = fmaf(fg, csm[u * 64 + b], ig * gg);
            float h  = og * tanhfast(c);
            csm[u * 64 + b] = c;
            __stcs(&g_hsT[(size_t)step * (HH*BB) + (size_t)gu * BB + b], h);
            __nv_bfloat16 hh = __float2bfloat16(h);
            __nv_bfloat16 hl = __float2bfloat16(h - __bfloat162float(hh));
            int nxt = cur ^ 1;
            __nv_bfloat16* hw = g_hbf + (size_t)nxt * (2 * 512 * 72);
            hw[(size_t)gu * 72 + b] = hh;                     // hi plane
            hw[(size_t)(512 + gu) * 72 + b] = hl;             // lo plane
            if (step == TT - 1 && out_size >= TT*BB*OO + 2*BB*HH) {
                d_out[TT*BB*OO + (size_t)b * HH + gu] = h;
                d_out[TT*BB*OO + BB*HH + (size_t)b * HH + gu] = c;
            }
        }
        __threadfence();
        grid_sync();
        cur ^= 1;
    }
}

// ============================================================================
// Kernel 3: FC epilogue
// ============================================================================
__global__ void __launch_bounds__(320) fc_kernel(
    const float* __restrict__ fcw, const float* __restrict__ fcb,
    float* __restrict__ out)
{
    __shared__ float wsm[OO][HH];
    __shared__ float bsm[OO];
    const int t = blockIdx.x, tid = threadIdx.x;
    for (int s = tid; s < OO * HH; s += 320) wsm[s / HH][s % HH] = fcw[s];
    if (tid < OO) bsm[tid] = fcb[tid];
    __syncthreads();
    const int o = tid >> 6, b = tid & 63;
    const float* hp = g_hsT + (size_t)t * (HH * BB) + b;
    float acc = bsm[o];
    #pragma unroll 8
    for (int k = 0; k < HH; k++)
        acc = fmaf(__ldcs(hp + (size_t)k * BB), wsm[o][k], acc);
    out[(size_t)t * (BB * OO) + b * OO + o] = acc;
}

// ============================================================================
extern "C" void kernel_launch(void* const* d_in, const int* in_sizes, int n_in,
                              void* d_out, int out_size) {
    const float* x   = (const float*)d_in[0];
    const float* Wih = (const float*)d_in[1];
    const float* Whh = (const float*)d_in[2];
    const float* bih = (const float*)d_in[3];
    const float* bhh = (const float*)d_in[4];
    const float* fcw = (const float*)d_in[5];
    const float* fcb = (const float*)d_in[6];
    float* out = (float*)d_out;

    cudaFuncSetAttribute(lstm_rec_mma,
                         cudaFuncAttributeMaxDynamicSharedMemorySize, REC_SMEM);
    cudaFuncSetAttribute(pregemm_mma,
                         cudaFuncAttributeMaxDynamicSharedMemorySize, PG_SMEM);

    prep_whh<<<G4, 128>>>(Whh);
    prep_wih<<<G4, 128>>>(Wih);
    prep_x<<<TT, 256>>>(x);
    pregemm_mma<<<TT * 16, 256, PG_SMEM>>>(bih, bhh);
    lstm_rec_mma<<<REC_CTAS, 256, REC_SMEM>>>(out, out_size);
    fc_kernel<<<TT, 320>>>(fcw, fcb, out);
}